// round 13
// baseline (speedup 1.0000x reference)
#include <cuda_runtime.h>
#include <cuda_bf16.h>
#include <math.h>
#include <stdint.h>

#define BB 1024
#define SS 100
#define HH 512
#define GG 1536   // 3*H
#define NUSR 1000

// ---------------------------------------------------------------------------
// Scratch (device globals: allowed; no runtime allocation)
// ---------------------------------------------------------------------------
__device__ float g_xproj[(size_t)BB * SS * GG];            // [B,S,3H] fp32
__device__ __nv_bfloat16 g_xh[(size_t)BB * SS * HH];       // X hi
__device__ __nv_bfloat16 g_xl[(size_t)BB * SS * HH];       // X lo
__device__ __nv_bfloat16 g_wh[(size_t)GG * HH];            // W_ih hi
__device__ __nv_bfloat16 g_wl[(size_t)GG * HH];            // W_ih lo
__device__ __nv_bfloat16 g_whhh[(size_t)GG * HH];          // W_hh hi
__device__ __nv_bfloat16 g_whhl[(size_t)GG * HH];          // W_hh lo
__device__ __nv_bfloat16 g_hh[(size_t)BB * 128 * HH];      // h for attention, hi (rows 100..127 stay 0)
__device__ __nv_bfloat16 g_hl[(size_t)BB * 128 * HH];      // h for attention, lo
__device__ __nv_bfloat16 g_hbh[(size_t)2 * BB * HH];       // h double buffer, hi
__device__ __nv_bfloat16 g_hbl[(size_t)2 * BB * HH];       // h double buffer, lo
__device__ float g_hstate[(size_t)BB * HH];                // exact fp32 h
__device__ unsigned g_bar[16];                             // spin barriers (memset each launch)

// ---------------------------------------------------------------------------
// Portable tensor-core primitives (compile for compute_103, no 'a' features)
// ---------------------------------------------------------------------------
__device__ __forceinline__ uint32_t smem_u32(const void* p) {
    uint32_t a;
    asm("{ .reg .u64 t; cvta.to.shared.u64 t, %1; cvt.u32.u64 %0, t; }"
        : "=r"(a) : "l"(p));
    return a;
}

#define CP_ASYNC16(sa, ga) \
    asm volatile("cp.async.cg.shared.global [%0], [%1], 16;" :: "r"(sa), "l"(ga))
#define CP_COMMIT() asm volatile("cp.async.commit_group;")
#define CP_WAIT1() asm volatile("cp.async.wait_group 1;" ::: "memory")
#define CP_WAIT0() asm volatile("cp.async.wait_group 0;" ::: "memory")

#define LDMX4(r0, r1, r2, r3, a) \
    asm volatile("ldmatrix.sync.aligned.m8n8.x4.shared.b16 {%0,%1,%2,%3}, [%4];" \
                 : "=r"(r0), "=r"(r1), "=r"(r2), "=r"(r3) : "r"(a))

#define LDMX2(r0, r1, a) \
    asm volatile("ldmatrix.sync.aligned.m8n8.x2.shared.b16 {%0,%1}, [%2];" \
                 : "=r"(r0), "=r"(r1) : "r"(a))

#define MMA_BF16(d, a, b) \
    asm volatile( \
        "mma.sync.aligned.m16n8k16.row.col.f32.bf16.bf16.f32 " \
        "{%0,%1,%2,%3}, {%4,%5,%6,%7}, {%8,%9}, {%0,%1,%2,%3};" \
        : "+f"((d)[0]), "+f"((d)[1]), "+f"((d)[2]), "+f"((d)[3]) \
        : "r"((a)[0]), "r"((a)[1]), "r"((a)[2]), "r"((a)[3]), \
          "r"((b)[0]), "r"((b)[1]))

// fp32 -> bf16 hi/lo split of 8 values, packed as uint4 each
__device__ __forceinline__ void cvt8(const float* f, uint4& hv, uint4& lv) {
    union { __nv_bfloat16 h[8]; uint4 u; } H;
    union { __nv_bfloat16 h[8]; uint4 u; } L;
#pragma unroll
    for (int j = 0; j < 8; j++) {
        __nv_bfloat16 hh = __float2bfloat16(f[j]);
        H.h[j] = hh;
        L.h[j] = __float2bfloat16(f[j] - __bfloat162float(hh));
    }
    hv = H.u; lv = L.u;
}

// ---------------------------------------------------------------------------
// Kernel A: fp32 -> bf16 hi/lo split (generic, float4-granular)
// ---------------------------------------------------------------------------
__global__ void k_split(const float* __restrict__ src, __nv_bfloat16* __restrict__ hi,
                        __nv_bfloat16* __restrict__ lo, size_t n4) {
    size_t i = (size_t)blockIdx.x * 256 + threadIdx.x;
    if (i >= n4) return;
    float4 v = ((const float4*)src)[i];
    float f[4] = {v.x, v.y, v.z, v.w};
    union { __nv_bfloat16 h[4]; uint2 u; } H;
    union { __nv_bfloat16 h[4]; uint2 u; } L;
#pragma unroll
    for (int j = 0; j < 4; j++) {
        __nv_bfloat16 hh = __float2bfloat16(f[j]);
        H.h[j] = hh;
        L.h[j] = __float2bfloat16(f[j] - __bfloat162float(hh));
    }
    *(uint2*)(hi + i * 4) = H.u;
    *(uint2*)(lo + i * 4) = L.u;
}

// ---------------------------------------------------------------------------
// Kernel 1: x_proj = X @ W_ih^T + b_ih  via mma.sync bf16 split-3.
// 3-stage cp.async ring.  R13: MMA issue reordered into 3 passes per mi so
// dependent HMMA (same accumulator) are 4 apart instead of back-to-back.
// ---------------------------------------------------------------------------
#define XP_AH 0
#define XP_AL 6144
#define XP_BH 12288
#define XP_BL 24576
#define XP_STG 36864
#define XP_SMEM (3 * XP_STG)

__global__ void __launch_bounds__(512, 1)
k_xproj_mma(const float* __restrict__ bias) {
    extern __shared__ char smx[];
    const uint32_t sb = smem_u32(smx);
    const int tid = threadIdx.x;
    const int wid = tid >> 5, lane = tid & 31;
    const int wm = wid >> 3, wn = wid & 7;
    const int bm = blockIdx.x;
    const int bn = blockIdx.y;
    const size_t m0 = (size_t)bm * 128;
    const size_t n0 = (size_t)bn * 256;

    const int ia  = tid & 255;
    const int ar  = ia >> 1, ac = ia & 1;
    const int br  = tid >> 1, bc = tid & 1;
    const bool isAl = (tid >= 256);
    const __nv_bfloat16* gA = isAl ? g_xl : g_xh;
    const uint32_t a_dst = (isAl ? XP_AL : XP_AH) + ar * 48 + ac * 16;

    float acc[4][4][4];
#pragma unroll
    for (int i = 0; i < 4; i++)
#pragma unroll
        for (int j = 0; j < 4; j++)
#pragma unroll
            for (int q = 0; q < 4; q++) acc[i][j][q] = 0.f;

    const uint32_t a_lane_off =
        (uint32_t)((wm * 64 + (lane & 15)) * 48 + (lane >> 4) * 16);
    const uint32_t b_lane_off =
        (uint32_t)((wn * 32 + (lane & 7) + (lane >> 4) * 8) * 48 +
                   ((lane >> 3) & 1) * 16);

#pragma unroll
    for (int s = 0; s < 2; s++) {
        uint32_t st = sb + (uint32_t)s * XP_STG;
        const int k0 = s * 16;
        CP_ASYNC16(st + a_dst, gA + (m0 + ar) * 512 + k0 + ac * 8);
        CP_ASYNC16(st + XP_BH + br * 48 + bc * 16,
                   g_wh + (n0 + br) * 512 + k0 + bc * 8);
        CP_ASYNC16(st + XP_BL + br * 48 + bc * 16,
                   g_wl + (n0 + br) * 512 + k0 + bc * 8);
        CP_COMMIT();
    }

    int slot = 0, slot2 = 2;
    for (int c = 0; c < 32; c++) {
        if (c < 31) CP_WAIT1(); else CP_WAIT0();
        __syncthreads();
        if (c + 2 < 32) {
            const int k0 = (c + 2) * 16;
            uint32_t st = sb + (uint32_t)slot2 * XP_STG;
            CP_ASYNC16(st + a_dst, gA + (m0 + ar) * 512 + k0 + ac * 8);
            CP_ASYNC16(st + XP_BH + br * 48 + bc * 16,
                       g_wh + (n0 + br) * 512 + k0 + bc * 8);
            CP_ASYNC16(st + XP_BL + br * 48 + bc * 16,
                       g_wl + (n0 + br) * 512 + k0 + bc * 8);
            CP_COMMIT();
        }
        const uint32_t cur = sb + (uint32_t)slot * XP_STG;

        uint32_t bh[4][2], bl[4][2];
        {
            uint32_t r0, r1, r2, r3;
            LDMX4(r0, r1, r2, r3, cur + XP_BH + b_lane_off);
            bh[0][0] = r0; bh[0][1] = r1; bh[1][0] = r2; bh[1][1] = r3;
            LDMX4(r0, r1, r2, r3, cur + XP_BH + b_lane_off + 16 * 48);
            bh[2][0] = r0; bh[2][1] = r1; bh[3][0] = r2; bh[3][1] = r3;
            LDMX4(r0, r1, r2, r3, cur + XP_BL + b_lane_off);
            bl[0][0] = r0; bl[0][1] = r1; bl[1][0] = r2; bl[1][1] = r3;
            LDMX4(r0, r1, r2, r3, cur + XP_BL + b_lane_off + 16 * 48);
            bl[2][0] = r0; bl[2][1] = r1; bl[3][0] = r2; bl[3][1] = r3;
        }
#pragma unroll
        for (int mi = 0; mi < 4; mi++) {
            uint32_t ah[4], al[4];
            LDMX4(ah[0], ah[1], ah[2], ah[3], cur + XP_AH + a_lane_off + mi * 16 * 48);
            LDMX4(al[0], al[1], al[2], al[3], cur + XP_AL + a_lane_off + mi * 16 * 48);
            // pass 1: ah x bh  (4 distinct accumulators)
#pragma unroll
            for (int nj = 0; nj < 4; nj++) MMA_BF16(acc[mi][nj], ah, bh[nj]);
            // pass 2: ah x bl
#pragma unroll
            for (int nj = 0; nj < 4; nj++) MMA_BF16(acc[mi][nj], ah, bl[nj]);
            // pass 3: al x bh
#pragma unroll
            for (int nj = 0; nj < 4; nj++) MMA_BF16(acc[mi][nj], al, bh[nj]);
        }
        slot = (slot == 2) ? 0 : slot + 1;
        slot2 = (slot2 == 2) ? 0 : slot2 + 1;
    }

    const int q = lane >> 2, cc = (lane & 3) * 2;
#pragma unroll
    for (int mi = 0; mi < 4; mi++) {
        const size_t r0 = m0 + wm * 64 + mi * 16 + q;
#pragma unroll
        for (int nj = 0; nj < 4; nj++) {
            const size_t nn = n0 + wn * 32 + nj * 8 + cc;
            float b0 = __ldg(bias + nn), b1 = __ldg(bias + nn + 1);
            float2 v0 = {acc[mi][nj][0] + b0, acc[mi][nj][1] + b1};
            float2 v1 = {acc[mi][nj][2] + b0, acc[mi][nj][3] + b1};
            *(float2*)(g_xproj + r0 * GG + nn) = v0;
            *(float2*)(g_xproj + (r0 + 8) * GG + nn) = v1;
        }
    }
}

// ---------------------------------------------------------------------------
// Kernel 2: persistent mma GRU (R12 512-thread shape).  R13: A-frags for both
// mi preloaded, MMA issued in 3 passes of 6 distinct accumulators.
// ---------------------------------------------------------------------------
#define GRU_WH 0
#define GRU_WL 98304
#define GRU_AST 196608
#define GRU_SMEM (196608 + 24576)

__global__ void __launch_bounds__(512, 1)
k_gru_mma(const float* __restrict__ h0, const float* __restrict__ bhh) {
    extern __shared__ char smx[];
    const uint32_t sb = smem_u32(smx);
    const int tid = threadIdx.x;
    const int wid = tid >> 5, lane = tid & 31;
    const int wm = wid >> 2, wn = wid & 3;     // 4 x 4 warps
    const int ns = blockIdx.x;
    const int mt = blockIdx.y;
    const int cid = mt * 16 + ns;
    const int mrow0 = mt * 128;

#pragma unroll
    for (int qq = 0; qq < 12; qq++) {
        int gi = tid + 512 * qq;
        int lr = gi >> 6, g16 = gi & 63;
        int grow = (lr >> 5) * 512 + ns * 32 + (lr & 31);
        uint32_t phys = (uint32_t)lr * 1024 + (uint32_t)((g16 ^ (lr & 7)) << 4);
        CP_ASYNC16(sb + GRU_WH + phys, g_whhh + (size_t)grow * 512 + g16 * 8);
        CP_ASYNC16(sb + GRU_WL + phys, g_whhl + (size_t)grow * 512 + g16 * 8);
    }
    CP_COMMIT();

#pragma unroll
    for (int qq = 0; qq < 2; qq++) {
        int idx = tid + 512 * qq;
        int r = idx >> 7, cp4 = (idx & 127) * 4;
        size_t o = (size_t)(cid * 8 + r) * 512 + cp4;
        float4 v = *(const float4*)(h0 + o);
        *(float4*)(g_hstate + o) = v;
        float f[4] = {v.x, v.y, v.z, v.w};
        union { __nv_bfloat16 h[4]; uint2 u; } H;
        union { __nv_bfloat16 h[4]; uint2 u; } L;
#pragma unroll
        for (int j = 0; j < 4; j++) {
            __nv_bfloat16 hh = __float2bfloat16(f[j]);
            H.h[j] = hh;
            L.h[j] = __float2bfloat16(f[j] - __bfloat162float(hh));
        }
        *(uint2*)(g_hbh + o) = H.u;
        *(uint2*)(g_hbl + o) = L.u;
    }
    __threadfence();
    __syncthreads();
    if (tid == 0) {
        atomicAdd(&g_bar[8], 1u);
        volatile unsigned* p = &g_bar[8];
        while (*p < 128u) {}
    }
    __syncthreads();
    __threadfence();
    CP_WAIT0();
    __syncthreads();

    const int ar = tid & 255, ahf = (ar & 1);
    const int arow = ar >> 1;
    const bool isAlo = (tid >= 256);
    const uint32_t a_cp_dst = (isAlo ? 6144u : 0u) + arow * 48 + ahf * 16;
    const __nv_bfloat16* g_hb_sel[2] = {g_hbh, g_hbl};

    const uint32_t a_base =
        (uint32_t)((wm * 32 + (lane & 15)) * 48 + (lane >> 4) * 16);
    int lrB[3];
#pragma unroll
    for (int g = 0; g < 3; g++) lrB[g] = g * 32 + wn * 8 + (lane & 7);
    const int kbit = (lane >> 3) & 1;
    const int qrow = lane >> 2, cc = (lane & 3) * 2;
    const int c0 = ns * 32 + wn * 8 + cc;
    float bhg[3][2];
#pragma unroll
    for (int g = 0; g < 3; g++) {
        bhg[g][0] = __ldg(bhh + g * 512 + c0);
        bhg[g][1] = __ldg(bhh + g * 512 + c0 + 1);
    }

    unsigned bar_target = 16;
    for (int t = 0; t < SS; t++) {
        const int cur = t & 1, nxt = cur ^ 1;
        const __nv_bfloat16* hsrc =
            g_hb_sel[isAlo ? 1 : 0] + (size_t)cur * (BB * HH);

        {
            uint32_t st = sb + GRU_AST;
            CP_ASYNC16(st + a_cp_dst,
                       hsrc + (size_t)(mrow0 + arow) * 512 + ahf * 8);
            CP_COMMIT();
        }

        float acc[2][3][4];
#pragma unroll
        for (int i = 0; i < 2; i++)
#pragma unroll
            for (int g = 0; g < 3; g++)
#pragma unroll
                for (int z = 0; z < 4; z++) acc[i][g][z] = 0.f;

        for (int c = 0; c < 32; c++) {
            CP_WAIT0();
            __syncthreads();
            if (c < 31) {
                uint32_t st = sb + GRU_AST + (uint32_t)((c + 1) & 1) * 12288;
                const int kb = (c + 1) * 16 + ahf * 8;
                CP_ASYNC16(st + a_cp_dst,
                           hsrc + (size_t)(mrow0 + arow) * 512 + kb);
                CP_COMMIT();
            }
            const uint32_t cs = sb + GRU_AST + (uint32_t)(c & 1) * 12288;

            uint32_t bhf[3][2], blf[3][2];
#pragma unroll
            for (int g = 0; g < 3; g++) {
                int g16 = 2 * c + kbit;
                uint32_t phys = (uint32_t)lrB[g] * 1024 +
                                (uint32_t)((g16 ^ (lrB[g] & 7)) << 4);
                LDMX2(bhf[g][0], bhf[g][1], sb + GRU_WH + phys);
                LDMX2(blf[g][0], blf[g][1], sb + GRU_WL + phys);
            }
            uint32_t ah[2][4], al[2][4];
#pragma unroll
            for (int mi = 0; mi < 2; mi++) {
                LDMX4(ah[mi][0], ah[mi][1], ah[mi][2], ah[mi][3],
                      cs + a_base + mi * 768);
                LDMX4(al[mi][0], al[mi][1], al[mi][2], al[mi][3],
                      cs + 6144 + a_base + mi * 768);
            }
            // 3 passes over 6 distinct accumulators (dep distance 6)
#pragma unroll
            for (int mi = 0; mi < 2; mi++)
#pragma unroll
                for (int g = 0; g < 3; g++) MMA_BF16(acc[mi][g], ah[mi], bhf[g]);
#pragma unroll
            for (int mi = 0; mi < 2; mi++)
#pragma unroll
                for (int g = 0; g < 3; g++) MMA_BF16(acc[mi][g], ah[mi], blf[g]);
#pragma unroll
            for (int mi = 0; mi < 2; mi++)
#pragma unroll
                for (int g = 0; g < 3; g++) MMA_BF16(acc[mi][g], al[mi], bhf[g]);
        }
        __syncthreads();

#pragma unroll
        for (int mi = 0; mi < 2; mi++) {
#pragma unroll
            for (int hp = 0; hp < 2; hp++) {
                const int b = mrow0 + wm * 32 + mi * 16 + qrow + hp * 8;
                const size_t xb = ((size_t)b * SS + t) * GG + c0;
                float xr0 = g_xproj[xb],        xr1 = g_xproj[xb + 1];
                float xz0 = g_xproj[xb + 512],  xz1 = g_xproj[xb + 513];
                float xn0 = g_xproj[xb + 1024], xn1 = g_xproj[xb + 1025];
                float2 hold = *(const float2*)(g_hstate + (size_t)b * 512 + c0);
                float hr0 = acc[mi][0][hp * 2 + 0] + bhg[0][0];
                float hr1 = acc[mi][0][hp * 2 + 1] + bhg[0][1];
                float hz0 = acc[mi][1][hp * 2 + 0] + bhg[1][0];
                float hz1 = acc[mi][1][hp * 2 + 1] + bhg[1][1];
                float hn0 = acc[mi][2][hp * 2 + 0] + bhg[2][0];
                float hn1 = acc[mi][2][hp * 2 + 1] + bhg[2][1];
                float rg0 = 1.f / (1.f + expf(-(xr0 + hr0)));
                float rg1 = 1.f / (1.f + expf(-(xr1 + hr1)));
                float zg0 = 1.f / (1.f + expf(-(xz0 + hz0)));
                float zg1 = 1.f / (1.f + expf(-(xz1 + hz1)));
                float ng0 = tanhf(xn0 + rg0 * hn0);
                float ng1 = tanhf(xn1 + rg1 * hn1);
                float h0n = (1.f - zg0) * ng0 + zg0 * hold.x;
                float h1n = (1.f - zg1) * ng1 + zg1 * hold.y;
                float2 hsv = {h0n, h1n};
                *(float2*)(g_hstate + (size_t)b * 512 + c0) = hsv;
                __nv_bfloat16 p0 = __float2bfloat16(h0n);
                __nv_bfloat16 p1 = __float2bfloat16(h1n);
                __nv_bfloat16 q0 = __float2bfloat16(h0n - __bfloat162float(p0));
                __nv_bfloat16 q1 = __float2bfloat16(h1n - __bfloat162float(p1));
                __nv_bfloat162 ph = __halves2bfloat162(p0, p1);
                __nv_bfloat162 pl = __halves2bfloat162(q0, q1);
                size_t ob = (size_t)nxt * (BB * HH) + (size_t)b * 512 + c0;
                *(__nv_bfloat162*)(g_hbh + ob) = ph;
                *(__nv_bfloat162*)(g_hbl + ob) = pl;
                size_t oa = ((size_t)b * 128 + t) * 512 + c0;
                *(__nv_bfloat162*)(g_hh + oa) = ph;
                *(__nv_bfloat162*)(g_hl + oa) = pl;
            }
        }
        __threadfence();
        __syncthreads();
        if (tid == 0) {
            atomicAdd(&g_bar[mt], 1u);
            volatile unsigned* p = &g_bar[mt];
            while (*p < bar_target) {}
        }
        __syncthreads();
        __threadfence();
        bar_target += 16;
    }
}

// ---------------------------------------------------------------------------
// Kernel 3: attention via mma.sync (2-stage).  Wa consumed fp32, converted in
// SMEM (exact col-sum C folded in).  R13: MMA passes reordered, dep dist 4.
// ---------------------------------------------------------------------------
#define AT_BA 0
#define AT_WS 2048
#define AT_CS 4096
#define AT_SC 4608
#define AT_BASE 5120
#define AT_AH 0
#define AT_AL 6144
#define AT_BF 12288
#define AT_BH 22528
#define AT_BL 28672
#define AT_STG 34816
#define AT_SMEM (AT_BASE + 2 * AT_STG)

__global__ void __launch_bounds__(256, 1)
k_attn_mma(const float* __restrict__ reps, const int* __restrict__ counts,
           const int* __restrict__ users, const float* __restrict__ Wa,
           const float* __restrict__ ba, const float* __restrict__ Wsv,
           float* __restrict__ outp) {
    extern __shared__ char smx[];
    const uint32_t sb = smem_u32(smx);
    float* ba_s  = (float*)(smx + AT_BA);
    float* ws_s  = (float*)(smx + AT_WS);
    float* C_s   = (float*)(smx + AT_CS);
    float* score = (float*)(smx + AT_SC);
    const int tid = threadIdx.x;
    const int wid = tid >> 5, lane = tid & 31;
    const int wm = wid >> 2, wn = wid & 3;
    const int b = blockIdx.x;
    const int cnt = counts[b];
    const int u = users[b];

    ba_s[tid]       = ba[(size_t)u * 512 + tid];
    ba_s[tid + 256] = ba[(size_t)u * 512 + 256 + tid];
    ws_s[tid]       = Wsv[(size_t)u * 512 + tid];
    ws_s[tid + 256] = Wsv[(size_t)u * 512 + 256 + tid];
    if (tid < 128) score[tid] = 0.f;
    __syncthreads();

    const __nv_bfloat16* Ahg = g_hh + (size_t)b * 128 * 512;
    const __nv_bfloat16* Alg = g_hl + (size_t)b * 128 * 512;
    const float* Bg = Wa + (size_t)u * 512 * 512;

    const int tr = tid >> 1, tc = tid & 1;
    const uint32_t a_lane_off =
        (uint32_t)((wm * 64 + (lane & 15)) * 48 + (lane >> 4) * 16);
    const uint32_t b_lane_off =
        (uint32_t)((wn * 32 + (lane & 7) + (lane >> 4) * 8) * 48 +
                   ((lane >> 3) & 1) * 16);
    const int q = lane >> 2, cc = (lane & 3) * 2;
    const int mimax = (wm == 0) ? 4 : 3;

    {
        uint32_t st = sb + AT_BASE;
        CP_ASYNC16(st + AT_AH + tr * 48 + tc * 16, Ahg + tr * 512 + tc * 8);
        CP_ASYNC16(st + AT_AL + tr * 48 + tc * 16, Alg + tr * 512 + tc * 8);
        CP_ASYNC16(st + AT_BF + tr * 80 + tc * 32,      Bg + (size_t)tr * 512 + tc * 8);
        CP_ASYNC16(st + AT_BF + tr * 80 + tc * 32 + 16, Bg + (size_t)tr * 512 + tc * 8 + 4);
        CP_COMMIT();
    }

    float acc[4][4][4];
    float cacc = 0.f;
    for (int it = 0; it < 128; it++) {
        const int np = it >> 5, c = it & 31;
        if (c == 0) {
#pragma unroll
            for (int i = 0; i < 4; i++)
#pragma unroll
                for (int j = 0; j < 4; j++)
#pragma unroll
                    for (int z = 0; z < 4; z++) acc[i][j][z] = 0.f;
            cacc = 0.f;
        }
        char* stc = smx + AT_BASE + (size_t)(it & 1) * AT_STG;
        const uint32_t cur = sb + AT_BASE + (uint32_t)(it & 1) * AT_STG;
        if (it < 127) {
            const int np2 = (it + 1) >> 5, c2 = (it + 1) & 31;
            const int k0 = c2 * 16;
            uint32_t st = sb + AT_BASE + (uint32_t)((it + 1) & 1) * AT_STG;
            const float* brow = Bg + (size_t)(np2 * 128 + tr) * 512 + k0 + tc * 8;
            CP_ASYNC16(st + AT_AH + tr * 48 + tc * 16,
                       Ahg + tr * 512 + k0 + tc * 8);
            CP_ASYNC16(st + AT_AL + tr * 48 + tc * 16,
                       Alg + tr * 512 + k0 + tc * 8);
            CP_ASYNC16(st + AT_BF + tr * 80 + tc * 32, brow);
            CP_ASYNC16(st + AT_BF + tr * 80 + tc * 32 + 16, brow + 4);
            CP_COMMIT();
            CP_WAIT1();
        } else {
            CP_WAIT0();
        }
        __syncthreads();

        {
            float4 v0 = *(const float4*)(stc + AT_BF + tr * 80 + tc * 32);
            float4 v1 = *(const float4*)(stc + AT_BF + tr * 80 + tc * 32 + 16);
            float f[8] = {v0.x, v0.y, v0.z, v0.w, v1.x, v1.y, v1.z, v1.w};
            cacc += f[0] + f[1] + f[2] + f[3] + f[4] + f[5] + f[6] + f[7];
            uint4 hv, lv;
            cvt8(f, hv, lv);
            *(uint4*)(stc + AT_BH + tr * 48 + tc * 16) = hv;
            *(uint4*)(stc + AT_BL + tr * 48 + tc * 16) = lv;
        }
        if (c == 31) {
            float tot = cacc + __shfl_xor_sync(0xffffffffu, cacc, 1);
            if (tc == 0) C_s[tr] = tot;
        }
        __syncthreads();

        uint32_t bh[4][2], bl[4][2];
        {
            uint32_t r0, r1, r2, r3;
            LDMX4(r0, r1, r2, r3, cur + AT_BH + b_lane_off);
            bh[0][0] = r0; bh[0][1] = r1; bh[1][0] = r2; bh[1][1] = r3;
            LDMX4(r0, r1, r2, r3, cur + AT_BH + b_lane_off + 16 * 48);
            bh[2][0] = r0; bh[2][1] = r1; bh[3][0] = r2; bh[3][1] = r3;
            LDMX4(r0, r1, r2, r3, cur + AT_BL + b_lane_off);
            bl[0][0] = r0; bl[0][1] = r1; bl[1][0] = r2; bl[1][1] = r3;
            LDMX4(r0, r1, r2, r3, cur + AT_BL + b_lane_off + 16 * 48);
            bl[2][0] = r0; bl[2][1] = r1; bl[3][0] = r2; bl[3][1] = r3;
        }
#pragma unroll
        for (int mi = 0; mi < 4; mi++) {
            if (mi >= mimax) break;
            uint32_t ah[4], al[4];
            LDMX4(ah[0], ah[1], ah[2], ah[3], cur + AT_AH + a_lane_off + mi * 16 * 48);
            LDMX4(al[0], al[1], al[2], al[3], cur + AT_AL + a_lane_off + mi * 16 * 48);
#pragma unroll
            for (int nj = 0; nj < 4; nj++) MMA_BF16(acc[mi][nj], ah, bh[nj]);
#pragma unroll
            for (int nj = 0; nj < 4; nj++) MMA_BF16(acc[mi][nj], ah, bl[nj]);
#pragma unroll
            for (int nj = 0; nj < 4; nj++) MMA_BF16(acc[mi][nj], al, bh[nj]);
        }

        if (c == 31) {
#pragma unroll
            for (int mi = 0; mi < 4; mi++) {
                if (mi >= mimax) break;
                const int s0 = wm * 64 + mi * 16 + q;
#pragma unroll
                for (int half = 0; half < 2; half++) {
                    const int s = s0 + half * 8;
                    const bool valid = (s < 100);
                    const float msk = (valid && s >= cnt) ? 1000000.0f : 0.0f;
                    float psum = 0.f;
#pragma unroll
                    for (int nj = 0; nj < 4; nj++) {
                        const int ol = wn * 32 + nj * 8 + cc;
                        const int o0 = np * 128 + ol;
                        float a0 = acc[mi][nj][half * 2 + 0] + ba_s[o0] - msk * C_s[ol];
                        float a1 = acc[mi][nj][half * 2 + 1] + ba_s[o0 + 1] - msk * C_s[ol + 1];
                        psum += ws_s[o0] * tanhf(a0) + ws_s[o0 + 1] * tanhf(a1);
                    }
                    psum += __shfl_xor_sync(0xffffffffu, psum, 1);
                    psum += __shfl_xor_sync(0xffffffffu, psum, 2);
                    if ((lane & 3) == 0 && valid) atomicAdd(&score[s], psum);
                }
            }
        }
    }
    __syncthreads();

    if (tid < 32) {
        float mx = -1e30f;
        for (int s = tid; s < 100; s += 32) mx = fmaxf(mx, score[s]);
#pragma unroll
        for (int o = 16; o > 0; o >>= 1) mx = fmaxf(mx, __shfl_xor_sync(0xffffffffu, mx, o));
        float ssum = 0.f;
        for (int s = tid; s < 100; s += 32) {
            float e = expf(score[s] - mx);
            score[s] = e;
            ssum += e;
        }
#pragma unroll
        for (int o = 16; o > 0; o >>= 1) ssum += __shfl_xor_sync(0xffffffffu, ssum, o);
        float inv = 1.f / ssum;
        for (int s = tid; s < 100; s += 32) score[s] *= inv;
    }
    __syncthreads();

    const float* rb = reps + (size_t)b * (SS * HH);
    for (int h = tid; h < 512; h += 256) {
        float a0 = 0.f;
        for (int s = 0; s < 100; s++) a0 += score[s] * rb[s * 512 + h];
        outp[(size_t)b * 512 + h] = a0;
    }
}

// ---------------------------------------------------------------------------
extern "C" void kernel_launch(void* const* d_in, const int* in_sizes, int n_in,
                              void* d_out, int out_size) {
    const float* reps   = (const float*)d_in[0];
    const float* hidden = (const float*)d_in[1];
    const int*   counts = (const int*)d_in[2];
    const int*   users  = (const int*)d_in[3];
    const float* W_ih   = (const float*)d_in[4];
    const float* W_hh   = (const float*)d_in[5];
    const float* b_ih   = (const float*)d_in[6];
    const float* b_hh   = (const float*)d_in[7];
    const float* Wa     = (const float*)d_in[8];
    const float* ba     = (const float*)d_in[9];
    const float* Ws     = (const float*)d_in[10];
    // d_in[11] = bs: additive per-row constant on scores -> softmax-invariant.
    float* out = (float*)d_out;

    cudaFuncSetAttribute(k_xproj_mma, cudaFuncAttributeMaxDynamicSharedMemorySize,
                         XP_SMEM);
    cudaFuncSetAttribute(k_gru_mma, cudaFuncAttributeMaxDynamicSharedMemorySize,
                         GRU_SMEM);
    cudaFuncSetAttribute(k_attn_mma, cudaFuncAttributeMaxDynamicSharedMemorySize,
                         AT_SMEM);

    __nv_bfloat16 *xh, *xl, *wh, *wl, *whhh, *whhl;
    void* barp;
    cudaGetSymbolAddress((void**)&xh, g_xh);
    cudaGetSymbolAddress((void**)&xl, g_xl);
    cudaGetSymbolAddress((void**)&wh, g_wh);
    cudaGetSymbolAddress((void**)&wl, g_wl);
    cudaGetSymbolAddress((void**)&whhh, g_whhh);
    cudaGetSymbolAddress((void**)&whhl, g_whhl);
    cudaGetSymbolAddress(&barp, g_bar);

    const size_t nX  = (size_t)BB * SS * HH / 4;
    const size_t nW  = (size_t)GG * HH / 4;
    // Launch order arranged so k_gru_mma is launch index 5 (ncu -s 5 -c 1).
    k_split<<<(unsigned)((nX + 255) / 256), 256>>>(reps, xh, xl, nX);
    k_split<<<(unsigned)((nW + 255) / 256), 256>>>(W_ih, wh, wl, nW);
    k_split<<<(unsigned)((nW + 255) / 256), 256>>>(W_hh, whhh, whhl, nW);

    dim3 g1(800, 6);
    k_xproj_mma<<<g1, 512, XP_SMEM>>>(b_ih);
    cudaMemsetAsync(barp, 0, 16 * sizeof(unsigned));
    k_gru_mma<<<dim3(16, 8), 512, GRU_SMEM>>>(hidden, b_hh);
    k_attn_mma<<<BB, 256, AT_SMEM>>>(reps, counts, users, Wa, ba, Ws, out);
}

// round 15
// speedup vs baseline: 1.0688x; 1.0688x over previous
#include <cuda_runtime.h>
#include <cuda_bf16.h>
#include <math.h>
#include <stdint.h>

#define BB 1024
#define SS 100
#define HH 512
#define GG 1536   // 3*H
#define NUSR 1000

// ---------------------------------------------------------------------------
// Scratch (device globals: allowed; no runtime allocation)
// ---------------------------------------------------------------------------
__device__ float g_xproj[(size_t)BB * SS * GG];            // [B,S,3H] fp32
__device__ __nv_bfloat16 g_xh[(size_t)BB * SS * HH];       // X hi
__device__ __nv_bfloat16 g_xl[(size_t)BB * SS * HH];       // X lo
__device__ __nv_bfloat16 g_wh[(size_t)GG * HH];            // W_ih hi
__device__ __nv_bfloat16 g_wl[(size_t)GG * HH];            // W_ih lo
__device__ __nv_bfloat16 g_whhh[(size_t)GG * HH];          // W_hh hi
__device__ __nv_bfloat16 g_whhl[(size_t)GG * HH];          // W_hh lo
__device__ __nv_bfloat16 g_hh[(size_t)BB * 128 * HH];      // h for attention, hi (rows 100..127 stay 0)
__device__ __nv_bfloat16 g_hl[(size_t)BB * 128 * HH];      // h for attention, lo
__device__ __nv_bfloat16 g_hbh[(size_t)2 * BB * HH];       // h double buffer, hi
__device__ __nv_bfloat16 g_hbl[(size_t)2 * BB * HH];       // h double buffer, lo
__device__ float g_hstate[(size_t)BB * HH];                // exact fp32 h
__device__ unsigned g_bar[16];                             // spin barriers (memset each launch)

// ---------------------------------------------------------------------------
// Portable tensor-core primitives (compile for compute_103, no 'a' features)
// ---------------------------------------------------------------------------
__device__ __forceinline__ uint32_t smem_u32(const void* p) {
    uint32_t a;
    asm("{ .reg .u64 t; cvta.to.shared.u64 t, %1; cvt.u32.u64 %0, t; }"
        : "=r"(a) : "l"(p));
    return a;
}

#define CP_ASYNC16(sa, ga) \
    asm volatile("cp.async.cg.shared.global [%0], [%1], 16;" :: "r"(sa), "l"(ga))
#define CP_COMMIT() asm volatile("cp.async.commit_group;")
#define CP_WAIT1() asm volatile("cp.async.wait_group 1;" ::: "memory")
#define CP_WAIT0() asm volatile("cp.async.wait_group 0;" ::: "memory")

#define LDMX4(r0, r1, r2, r3, a) \
    asm volatile("ldmatrix.sync.aligned.m8n8.x4.shared.b16 {%0,%1,%2,%3}, [%4];" \
                 : "=r"(r0), "=r"(r1), "=r"(r2), "=r"(r3) : "r"(a))

#define LDMX2(r0, r1, a) \
    asm volatile("ldmatrix.sync.aligned.m8n8.x2.shared.b16 {%0,%1}, [%2];" \
                 : "=r"(r0), "=r"(r1) : "r"(a))

#define MMA_BF16(d, a, b) \
    asm volatile( \
        "mma.sync.aligned.m16n8k16.row.col.f32.bf16.bf16.f32 " \
        "{%0,%1,%2,%3}, {%4,%5,%6,%7}, {%8,%9}, {%0,%1,%2,%3};" \
        : "+f"((d)[0]), "+f"((d)[1]), "+f"((d)[2]), "+f"((d)[3]) \
        : "r"((a)[0]), "r"((a)[1]), "r"((a)[2]), "r"((a)[3]), \
          "r"((b)[0]), "r"((b)[1]))

// fp32 -> bf16 hi/lo split of 8 values, packed as uint4 each
__device__ __forceinline__ void cvt8(const float* f, uint4& hv, uint4& lv) {
    union { __nv_bfloat16 h[8]; uint4 u; } H;
    union { __nv_bfloat16 h[8]; uint4 u; } L;
#pragma unroll
    for (int j = 0; j < 8; j++) {
        __nv_bfloat16 hh = __float2bfloat16(f[j]);
        H.h[j] = hh;
        L.h[j] = __float2bfloat16(f[j] - __bfloat162float(hh));
    }
    hv = H.u; lv = L.u;
}

// ---------------------------------------------------------------------------
// Kernel A: fp32 -> bf16 hi/lo split (generic, float4-granular)
// ---------------------------------------------------------------------------
__global__ void k_split(const float* __restrict__ src, __nv_bfloat16* __restrict__ hi,
                        __nv_bfloat16* __restrict__ lo, size_t n4) {
    size_t i = (size_t)blockIdx.x * 256 + threadIdx.x;
    if (i >= n4) return;
    float4 v = ((const float4*)src)[i];
    float f[4] = {v.x, v.y, v.z, v.w};
    union { __nv_bfloat16 h[4]; uint2 u; } H;
    union { __nv_bfloat16 h[4]; uint2 u; } L;
#pragma unroll
    for (int j = 0; j < 4; j++) {
        __nv_bfloat16 hh = __float2bfloat16(f[j]);
        H.h[j] = hh;
        L.h[j] = __float2bfloat16(f[j] - __bfloat162float(hh));
    }
    *(uint2*)(hi + i * 4) = H.u;
    *(uint2*)(lo + i * 4) = L.u;
}

// ---------------------------------------------------------------------------
// Kernel 1: x_proj = X @ W_ih^T + b_ih  via mma.sync bf16 split-3.
// R15: 256-thread CTAs, tile 128x128, 3-stage cp.async ring, 2 CTAs/SM.
// Ring order (proven in R11/R12): prologue fills stages 0,1; per iter c:
//   wait_group 1 (stage c complete: 2 groups were in flight) -> sync
//   -> issue stage c+2 into slot (c+2)%3 (readers retired by the sync)
//   -> ldmatrix+mma on slot c%3.
// Two CTAs/SM = two independent barrier domains covering each other's stalls.
// Stage: AH 6144 | AL 6144 | BH 6144 | BL 6144 = 24576 B; x3 = 73728 B.
// ---------------------------------------------------------------------------
#define XP_AH 0
#define XP_AL 6144
#define XP_BH 12288
#define XP_BL 18432
#define XP_STG 24576
#define XP_SMEM (3 * XP_STG)

__global__ void __launch_bounds__(256, 2)
k_xproj_mma(const float* __restrict__ bias) {
    extern __shared__ char smx[];
    const uint32_t sb = smem_u32(smx);
    const int tid = threadIdx.x;
    const int wid = tid >> 5, lane = tid & 31;
    const int wm = wid >> 2, wn = wid & 3;      // 2m x 4n warps, warp tile 64x32
    const int bm = blockIdx.x;                  // 0..799
    const int bn = blockIdx.y;                  // 0..11
    const size_t m0 = (size_t)bm * 128;
    const size_t n0 = (size_t)bn * 128;

    const int tr = tid >> 1, tc = tid & 1;      // cp.async: 128 rows x 2 halves

    float acc[4][4][4];
#pragma unroll
    for (int i = 0; i < 4; i++)
#pragma unroll
        for (int j = 0; j < 4; j++)
#pragma unroll
            for (int q = 0; q < 4; q++) acc[i][j][q] = 0.f;

    const uint32_t a_lane_off =
        (uint32_t)((wm * 64 + (lane & 15)) * 48 + (lane >> 4) * 16);
    const uint32_t b_lane_off =
        (uint32_t)((wn * 32 + (lane & 7) + (lane >> 4) * 8) * 48 +
                   ((lane >> 3) & 1) * 16);

    // prologue: issue stages 0 and 1 (two groups in flight)
#pragma unroll
    for (int s = 0; s < 2; s++) {
        uint32_t st = sb + (uint32_t)s * XP_STG;
        const int k0 = s * 16;
        CP_ASYNC16(st + XP_AH + tr * 48 + tc * 16,
                   g_xh + (m0 + tr) * 512 + k0 + tc * 8);
        CP_ASYNC16(st + XP_AL + tr * 48 + tc * 16,
                   g_xl + (m0 + tr) * 512 + k0 + tc * 8);
        CP_ASYNC16(st + XP_BH + tr * 48 + tc * 16,
                   g_wh + (n0 + tr) * 512 + k0 + tc * 8);
        CP_ASYNC16(st + XP_BL + tr * 48 + tc * 16,
                   g_wl + (n0 + tr) * 512 + k0 + tc * 8);
        CP_COMMIT();
    }

    int slot = 0, slot2 = 2;                    // slot = c%3, slot2 = (c+2)%3
    for (int c = 0; c < 32; c++) {
        if (c < 31) CP_WAIT1(); else CP_WAIT0();
        __syncthreads();
        if (c + 2 < 32) {
            const int k0 = (c + 2) * 16;
            uint32_t st = sb + (uint32_t)slot2 * XP_STG;
            CP_ASYNC16(st + XP_AH + tr * 48 + tc * 16,
                       g_xh + (m0 + tr) * 512 + k0 + tc * 8);
            CP_ASYNC16(st + XP_AL + tr * 48 + tc * 16,
                       g_xl + (m0 + tr) * 512 + k0 + tc * 8);
            CP_ASYNC16(st + XP_BH + tr * 48 + tc * 16,
                       g_wh + (n0 + tr) * 512 + k0 + tc * 8);
            CP_ASYNC16(st + XP_BL + tr * 48 + tc * 16,
                       g_wl + (n0 + tr) * 512 + k0 + tc * 8);
            CP_COMMIT();
        }
        const uint32_t cur = sb + (uint32_t)slot * XP_STG;

        uint32_t bh[4][2], bl[4][2];
        {
            uint32_t r0, r1, r2, r3;
            LDMX4(r0, r1, r2, r3, cur + XP_BH + b_lane_off);
            bh[0][0] = r0; bh[0][1] = r1; bh[1][0] = r2; bh[1][1] = r3;
            LDMX4(r0, r1, r2, r3, cur + XP_BH + b_lane_off + 16 * 48);
            bh[2][0] = r0; bh[2][1] = r1; bh[3][0] = r2; bh[3][1] = r3;
            LDMX4(r0, r1, r2, r3, cur + XP_BL + b_lane_off);
            bl[0][0] = r0; bl[0][1] = r1; bl[1][0] = r2; bl[1][1] = r3;
            LDMX4(r0, r1, r2, r3, cur + XP_BL + b_lane_off + 16 * 48);
            bl[2][0] = r0; bl[2][1] = r1; bl[3][0] = r2; bl[3][1] = r3;
        }
#pragma unroll
        for (int mi = 0; mi < 4; mi++) {
            uint32_t ah[4], al[4];
            LDMX4(ah[0], ah[1], ah[2], ah[3], cur + XP_AH + a_lane_off + mi * 16 * 48);
            LDMX4(al[0], al[1], al[2], al[3], cur + XP_AL + a_lane_off + mi * 16 * 48);
#pragma unroll
            for (int nj = 0; nj < 4; nj++) {
                MMA_BF16(acc[mi][nj], ah, bh[nj]);
                MMA_BF16(acc[mi][nj], ah, bl[nj]);
                MMA_BF16(acc[mi][nj], al, bh[nj]);
            }
        }
        slot = (slot == 2) ? 0 : slot + 1;
        slot2 = (slot2 == 2) ? 0 : slot2 + 1;
    }

    const int q = lane >> 2, cc = (lane & 3) * 2;
#pragma unroll
    for (int mi = 0; mi < 4; mi++) {
        const size_t r0 = m0 + wm * 64 + mi * 16 + q;
#pragma unroll
        for (int nj = 0; nj < 4; nj++) {
            const size_t nn = n0 + wn * 32 + nj * 8 + cc;
            float b0 = __ldg(bias + nn), b1 = __ldg(bias + nn + 1);
            float2 v0 = {acc[mi][nj][0] + b0, acc[mi][nj][1] + b1};
            float2 v1 = {acc[mi][nj][2] + b0, acc[mi][nj][3] + b1};
            *(float2*)(g_xproj + r0 * GG + nn) = v0;
            *(float2*)(g_xproj + (r0 + 8) * GG + nn) = v1;
        }
    }
}

// ---------------------------------------------------------------------------
// Kernel 2: persistent mma GRU (R12 512-thread shape, R12 issue order —
// byte-identical to the 4,780us passing version).
// ---------------------------------------------------------------------------
#define GRU_WH 0
#define GRU_WL 98304
#define GRU_AST 196608
#define GRU_SMEM (196608 + 24576)

__global__ void __launch_bounds__(512, 1)
k_gru_mma(const float* __restrict__ h0, const float* __restrict__ bhh) {
    extern __shared__ char smx[];
    const uint32_t sb = smem_u32(smx);
    const int tid = threadIdx.x;
    const int wid = tid >> 5, lane = tid & 31;
    const int wm = wid >> 2, wn = wid & 3;     // 4 x 4 warps
    const int ns = blockIdx.x;
    const int mt = blockIdx.y;
    const int cid = mt * 16 + ns;
    const int mrow0 = mt * 128;

#pragma unroll
    for (int qq = 0; qq < 12; qq++) {
        int gi = tid + 512 * qq;
        int lr = gi >> 6, g16 = gi & 63;
        int grow = (lr >> 5) * 512 + ns * 32 + (lr & 31);
        uint32_t phys = (uint32_t)lr * 1024 + (uint32_t)((g16 ^ (lr & 7)) << 4);
        CP_ASYNC16(sb + GRU_WH + phys, g_whhh + (size_t)grow * 512 + g16 * 8);
        CP_ASYNC16(sb + GRU_WL + phys, g_whhl + (size_t)grow * 512 + g16 * 8);
    }
    CP_COMMIT();

#pragma unroll
    for (int qq = 0; qq < 2; qq++) {
        int idx = tid + 512 * qq;
        int r = idx >> 7, cp4 = (idx & 127) * 4;
        size_t o = (size_t)(cid * 8 + r) * 512 + cp4;
        float4 v = *(const float4*)(h0 + o);
        *(float4*)(g_hstate + o) = v;
        float f[4] = {v.x, v.y, v.z, v.w};
        union { __nv_bfloat16 h[4]; uint2 u; } H;
        union { __nv_bfloat16 h[4]; uint2 u; } L;
#pragma unroll
        for (int j = 0; j < 4; j++) {
            __nv_bfloat16 hh = __float2bfloat16(f[j]);
            H.h[j] = hh;
            L.h[j] = __float2bfloat16(f[j] - __bfloat162float(hh));
        }
        *(uint2*)(g_hbh + o) = H.u;
        *(uint2*)(g_hbl + o) = L.u;
    }
    __threadfence();
    __syncthreads();
    if (tid == 0) {
        atomicAdd(&g_bar[8], 1u);
        volatile unsigned* p = &g_bar[8];
        while (*p < 128u) {}
    }
    __syncthreads();
    __threadfence();
    CP_WAIT0();
    __syncthreads();

    const int ar = tid & 255, ahf = (ar & 1);
    const int arow = ar >> 1;
    const bool isAlo = (tid >= 256);
    const uint32_t a_cp_dst = (isAlo ? 6144u : 0u) + arow * 48 + ahf * 16;
    const __nv_bfloat16* g_hb_sel[2] = {g_hbh, g_hbl};

    const uint32_t a_base =
        (uint32_t)((wm * 32 + (lane & 15)) * 48 + (lane >> 4) * 16);
    int lrB[3];
#pragma unroll
    for (int g = 0; g < 3; g++) lrB[g] = g * 32 + wn * 8 + (lane & 7);
    const int kbit = (lane >> 3) & 1;
    const int qrow = lane >> 2, cc = (lane & 3) * 2;
    const int c0 = ns * 32 + wn * 8 + cc;
    float bhg[3][2];
#pragma unroll
    for (int g = 0; g < 3; g++) {
        bhg[g][0] = __ldg(bhh + g * 512 + c0);
        bhg[g][1] = __ldg(bhh + g * 512 + c0 + 1);
    }

    unsigned bar_target = 16;
    for (int t = 0; t < SS; t++) {
        const int cur = t & 1, nxt = cur ^ 1;
        const __nv_bfloat16* hsrc =
            g_hb_sel[isAlo ? 1 : 0] + (size_t)cur * (BB * HH);

        {
            uint32_t st = sb + GRU_AST;
            CP_ASYNC16(st + a_cp_dst,
                       hsrc + (size_t)(mrow0 + arow) * 512 + ahf * 8);
            CP_COMMIT();
        }

        float acc[2][3][4];
#pragma unroll
        for (int i = 0; i < 2; i++)
#pragma unroll
            for (int g = 0; g < 3; g++)
#pragma unroll
                for (int z = 0; z < 4; z++) acc[i][g][z] = 0.f;

        for (int c = 0; c < 32; c++) {
            CP_WAIT0();
            __syncthreads();
            if (c < 31) {
                uint32_t st = sb + GRU_AST + (uint32_t)((c + 1) & 1) * 12288;
                const int kb = (c + 1) * 16 + ahf * 8;
                CP_ASYNC16(st + a_cp_dst,
                           hsrc + (size_t)(mrow0 + arow) * 512 + kb);
                CP_COMMIT();
            }
            const uint32_t cs = sb + GRU_AST + (uint32_t)(c & 1) * 12288;

            uint32_t bhf[3][2], blf[3][2];
#pragma unroll
            for (int g = 0; g < 3; g++) {
                int g16 = 2 * c + kbit;
                uint32_t phys = (uint32_t)lrB[g] * 1024 +
                                (uint32_t)((g16 ^ (lrB[g] & 7)) << 4);
                LDMX2(bhf[g][0], bhf[g][1], sb + GRU_WH + phys);
                LDMX2(blf[g][0], blf[g][1], sb + GRU_WL + phys);
            }
#pragma unroll
            for (int mi = 0; mi < 2; mi++) {
                uint32_t ah[4], al[4];
                LDMX4(ah[0], ah[1], ah[2], ah[3], cs + a_base + mi * 768);
                LDMX4(al[0], al[1], al[2], al[3], cs + 6144 + a_base + mi * 768);
#pragma unroll
                for (int g = 0; g < 3; g++) {
                    MMA_BF16(acc[mi][g], ah, bhf[g]);
                    MMA_BF16(acc[mi][g], ah, blf[g]);
                    MMA_BF16(acc[mi][g], al, bhf[g]);
                }
            }
        }
        __syncthreads();

#pragma unroll
        for (int mi = 0; mi < 2; mi++) {
#pragma unroll
            for (int hp = 0; hp < 2; hp++) {
                const int b = mrow0 + wm * 32 + mi * 16 + qrow + hp * 8;
                const size_t xb = ((size_t)b * SS + t) * GG + c0;
                float xr0 = g_xproj[xb],        xr1 = g_xproj[xb + 1];
                float xz0 = g_xproj[xb + 512],  xz1 = g_xproj[xb + 513];
                float xn0 = g_xproj[xb + 1024], xn1 = g_xproj[xb + 1025];
                float2 hold = *(const float2*)(g_hstate + (size_t)b * 512 + c0);
                float hr0 = acc[mi][0][hp * 2 + 0] + bhg[0][0];
                float hr1 = acc[mi][0][hp * 2 + 1] + bhg[0][1];
                float hz0 = acc[mi][1][hp * 2 + 0] + bhg[1][0];
                float hz1 = acc[mi][1][hp * 2 + 1] + bhg[1][1];
                float hn0 = acc[mi][2][hp * 2 + 0] + bhg[2][0];
                float hn1 = acc[mi][2][hp * 2 + 1] + bhg[2][1];
                float rg0 = 1.f / (1.f + expf(-(xr0 + hr0)));
                float rg1 = 1.f / (1.f + expf(-(xr1 + hr1)));
                float zg0 = 1.f / (1.f + expf(-(xz0 + hz0)));
                float zg1 = 1.f / (1.f + expf(-(xz1 + hz1)));
                float ng0 = tanhf(xn0 + rg0 * hn0);
                float ng1 = tanhf(xn1 + rg1 * hn1);
                float h0n = (1.f - zg0) * ng0 + zg0 * hold.x;
                float h1n = (1.f - zg1) * ng1 + zg1 * hold.y;
                float2 hsv = {h0n, h1n};
                *(float2*)(g_hstate + (size_t)b * 512 + c0) = hsv;
                __nv_bfloat16 p0 = __float2bfloat16(h0n);
                __nv_bfloat16 p1 = __float2bfloat16(h1n);
                __nv_bfloat16 q0 = __float2bfloat16(h0n - __bfloat162float(p0));
                __nv_bfloat16 q1 = __float2bfloat16(h1n - __bfloat162float(p1));
                __nv_bfloat162 ph = __halves2bfloat162(p0, p1);
                __nv_bfloat162 pl = __halves2bfloat162(q0, q1);
                size_t ob = (size_t)nxt * (BB * HH) + (size_t)b * 512 + c0;
                *(__nv_bfloat162*)(g_hbh + ob) = ph;
                *(__nv_bfloat162*)(g_hbl + ob) = pl;
                size_t oa = ((size_t)b * 128 + t) * 512 + c0;
                *(__nv_bfloat162*)(g_hh + oa) = ph;
                *(__nv_bfloat162*)(g_hl + oa) = pl;
            }
        }
        __threadfence();
        __syncthreads();
        if (tid == 0) {
            atomicAdd(&g_bar[mt], 1u);
            volatile unsigned* p = &g_bar[mt];
            while (*p < bar_target) {}
        }
        __syncthreads();
        __threadfence();
        bar_target += 16;
    }
}

// ---------------------------------------------------------------------------
// Kernel 3: attention via mma.sync (R12 2-stage form, byte-identical to the
// 4,780us passing version).
// ---------------------------------------------------------------------------
#define AT_BA 0
#define AT_WS 2048
#define AT_CS 4096
#define AT_SC 4608
#define AT_BASE 5120
#define AT_AH 0
#define AT_AL 6144
#define AT_BF 12288
#define AT_BH 22528
#define AT_BL 28672
#define AT_STG 34816
#define AT_SMEM (AT_BASE + 2 * AT_STG)

__global__ void __launch_bounds__(256, 1)
k_attn_mma(const float* __restrict__ reps, const int* __restrict__ counts,
           const int* __restrict__ users, const float* __restrict__ Wa,
           const float* __restrict__ ba, const float* __restrict__ Wsv,
           float* __restrict__ outp) {
    extern __shared__ char smx[];
    const uint32_t sb = smem_u32(smx);
    float* ba_s  = (float*)(smx + AT_BA);
    float* ws_s  = (float*)(smx + AT_WS);
    float* C_s   = (float*)(smx + AT_CS);
    float* score = (float*)(smx + AT_SC);
    const int tid = threadIdx.x;
    const int wid = tid >> 5, lane = tid & 31;
    const int wm = wid >> 2, wn = wid & 3;
    const int b = blockIdx.x;
    const int cnt = counts[b];
    const int u = users[b];

    ba_s[tid]       = ba[(size_t)u * 512 + tid];
    ba_s[tid + 256] = ba[(size_t)u * 512 + 256 + tid];
    ws_s[tid]       = Wsv[(size_t)u * 512 + tid];
    ws_s[tid + 256] = Wsv[(size_t)u * 512 + 256 + tid];
    if (tid < 128) score[tid] = 0.f;
    __syncthreads();

    const __nv_bfloat16* Ahg = g_hh + (size_t)b * 128 * 512;
    const __nv_bfloat16* Alg = g_hl + (size_t)b * 128 * 512;
    const float* Bg = Wa + (size_t)u * 512 * 512;

    const int tr = tid >> 1, tc = tid & 1;
    const uint32_t a_lane_off =
        (uint32_t)((wm * 64 + (lane & 15)) * 48 + (lane >> 4) * 16);
    const uint32_t b_lane_off =
        (uint32_t)((wn * 32 + (lane & 7) + (lane >> 4) * 8) * 48 +
                   ((lane >> 3) & 1) * 16);
    const int q = lane >> 2, cc = (lane & 3) * 2;
    const int mimax = (wm == 0) ? 4 : 3;

    {
        uint32_t st = sb + AT_BASE;
        CP_ASYNC16(st + AT_AH + tr * 48 + tc * 16, Ahg + tr * 512 + tc * 8);
        CP_ASYNC16(st + AT_AL + tr * 48 + tc * 16, Alg + tr * 512 + tc * 8);
        CP_ASYNC16(st + AT_BF + tr * 80 + tc * 32,      Bg + (size_t)tr * 512 + tc * 8);
        CP_ASYNC16(st + AT_BF + tr * 80 + tc * 32 + 16, Bg + (size_t)tr * 512 + tc * 8 + 4);
        CP_COMMIT();
    }

    float acc[4][4][4];
    float cacc = 0.f;
    for (int it = 0; it < 128; it++) {
        const int np = it >> 5, c = it & 31;
        if (c == 0) {
#pragma unroll
            for (int i = 0; i < 4; i++)
#pragma unroll
                for (int j = 0; j < 4; j++)
#pragma unroll
                    for (int z = 0; z < 4; z++) acc[i][j][z] = 0.f;
            cacc = 0.f;
        }
        char* stc = smx + AT_BASE + (size_t)(it & 1) * AT_STG;
        const uint32_t cur = sb + AT_BASE + (uint32_t)(it & 1) * AT_STG;
        if (it < 127) {
            const int np2 = (it + 1) >> 5, c2 = (it + 1) & 31;
            const int k0 = c2 * 16;
            uint32_t st = sb + AT_BASE + (uint32_t)((it + 1) & 1) * AT_STG;
            const float* brow = Bg + (size_t)(np2 * 128 + tr) * 512 + k0 + tc * 8;
            CP_ASYNC16(st + AT_AH + tr * 48 + tc * 16,
                       Ahg + tr * 512 + k0 + tc * 8);
            CP_ASYNC16(st + AT_AL + tr * 48 + tc * 16,
                       Alg + tr * 512 + k0 + tc * 8);
            CP_ASYNC16(st + AT_BF + tr * 80 + tc * 32, brow);
            CP_ASYNC16(st + AT_BF + tr * 80 + tc * 32 + 16, brow + 4);
            CP_COMMIT();
            CP_WAIT1();
        } else {
            CP_WAIT0();
        }
        __syncthreads();

        {
            float4 v0 = *(const float4*)(stc + AT_BF + tr * 80 + tc * 32);
            float4 v1 = *(const float4*)(stc + AT_BF + tr * 80 + tc * 32 + 16);
            float f[8] = {v0.x, v0.y, v0.z, v0.w, v1.x, v1.y, v1.z, v1.w};
            cacc += f[0] + f[1] + f[2] + f[3] + f[4] + f[5] + f[6] + f[7];
            uint4 hv, lv;
            cvt8(f, hv, lv);
            *(uint4*)(stc + AT_BH + tr * 48 + tc * 16) = hv;
            *(uint4*)(stc + AT_BL + tr * 48 + tc * 16) = lv;
        }
        if (c == 31) {
            float tot = cacc + __shfl_xor_sync(0xffffffffu, cacc, 1);
            if (tc == 0) C_s[tr] = tot;
        }
        __syncthreads();

        uint32_t bh[4][2], bl[4][2];
        {
            uint32_t r0, r1, r2, r3;
            LDMX4(r0, r1, r2, r3, cur + AT_BH + b_lane_off);
            bh[0][0] = r0; bh[0][1] = r1; bh[1][0] = r2; bh[1][1] = r3;
            LDMX4(r0, r1, r2, r3, cur + AT_BH + b_lane_off + 16 * 48);
            bh[2][0] = r0; bh[2][1] = r1; bh[3][0] = r2; bh[3][1] = r3;
            LDMX4(r0, r1, r2, r3, cur + AT_BL + b_lane_off);
            bl[0][0] = r0; bl[0][1] = r1; bl[1][0] = r2; bl[1][1] = r3;
            LDMX4(r0, r1, r2, r3, cur + AT_BL + b_lane_off + 16 * 48);
            bl[2][0] = r0; bl[2][1] = r1; bl[3][0] = r2; bl[3][1] = r3;
        }
#pragma unroll
        for (int mi = 0; mi < 4; mi++) {
            if (mi >= mimax) break;
            uint32_t ah[4], al[4];
            LDMX4(ah[0], ah[1], ah[2], ah[3], cur + AT_AH + a_lane_off + mi * 16 * 48);
            LDMX4(al[0], al[1], al[2], al[3], cur + AT_AL + a_lane_off + mi * 16 * 48);
#pragma unroll
            for (int nj = 0; nj < 4; nj++) {
                MMA_BF16(acc[mi][nj], ah, bh[nj]);
                MMA_BF16(acc[mi][nj], ah, bl[nj]);
                MMA_BF16(acc[mi][nj], al, bh[nj]);
            }
        }

        if (c == 31) {
#pragma unroll
            for (int mi = 0; mi < 4; mi++) {
                if (mi >= mimax) break;
                const int s0 = wm * 64 + mi * 16 + q;
#pragma unroll
                for (int half = 0; half < 2; half++) {
                    const int s = s0 + half * 8;
                    const bool valid = (s < 100);
                    const float msk = (valid && s >= cnt) ? 1000000.0f : 0.0f;
                    float psum = 0.f;
#pragma unroll
                    for (int nj = 0; nj < 4; nj++) {
                        const int ol = wn * 32 + nj * 8 + cc;
                        const int o0 = np * 128 + ol;
                        float a0 = acc[mi][nj][half * 2 + 0] + ba_s[o0] - msk * C_s[ol];
                        float a1 = acc[mi][nj][half * 2 + 1] + ba_s[o0 + 1] - msk * C_s[ol + 1];
                        psum += ws_s[o0] * tanhf(a0) + ws_s[o0 + 1] * tanhf(a1);
                    }
                    psum += __shfl_xor_sync(0xffffffffu, psum, 1);
                    psum += __shfl_xor_sync(0xffffffffu, psum, 2);
                    if ((lane & 3) == 0 && valid) atomicAdd(&score[s], psum);
                }
            }
        }
    }
    __syncthreads();

    if (tid < 32) {
        float mx = -1e30f;
        for (int s = tid; s < 100; s += 32) mx = fmaxf(mx, score[s]);
#pragma unroll
        for (int o = 16; o > 0; o >>= 1) mx = fmaxf(mx, __shfl_xor_sync(0xffffffffu, mx, o));
        float ssum = 0.f;
        for (int s = tid; s < 100; s += 32) {
            float e = expf(score[s] - mx);
            score[s] = e;
            ssum += e;
        }
#pragma unroll
        for (int o = 16; o > 0; o >>= 1) ssum += __shfl_xor_sync(0xffffffffu, ssum, o);
        float inv = 1.f / ssum;
        for (int s = tid; s < 100; s += 32) score[s] *= inv;
    }
    __syncthreads();

    const float* rb = reps + (size_t)b * (SS * HH);
    for (int h = tid; h < 512; h += 256) {
        float a0 = 0.f;
        for (int s = 0; s < 100; s++) a0 += score[s] * rb[s * 512 + h];
        outp[(size_t)b * 512 + h] = a0;
    }
}

// ---------------------------------------------------------------------------
extern "C" void kernel_launch(void* const* d_in, const int* in_sizes, int n_in,
                              void* d_out, int out_size) {
    const float* reps   = (const float*)d_in[0];
    const float* hidden = (const float*)d_in[1];
    const int*   counts = (const int*)d_in[2];
    const int*   users  = (const int*)d_in[3];
    const float* W_ih   = (const float*)d_in[4];
    const float* W_hh   = (const float*)d_in[5];
    const float* b_ih   = (const float*)d_in[6];
    const float* b_hh   = (const float*)d_in[7];
    const float* Wa     = (const float*)d_in[8];
    const float* ba     = (const float*)d_in[9];
    const float* Ws     = (const float*)d_in[10];
    // d_in[11] = bs: additive per-row constant on scores -> softmax-invariant.
    float* out = (float*)d_out;

    cudaFuncSetAttribute(k_xproj_mma, cudaFuncAttributeMaxDynamicSharedMemorySize,
                         XP_SMEM);
    cudaFuncSetAttribute(k_gru_mma, cudaFuncAttributeMaxDynamicSharedMemorySize,
                         GRU_SMEM);
    cudaFuncSetAttribute(k_attn_mma, cudaFuncAttributeMaxDynamicSharedMemorySize,
                         AT_SMEM);

    __nv_bfloat16 *xh, *xl, *wh, *wl, *whhh, *whhl;
    void* barp;
    cudaGetSymbolAddress((void**)&xh, g_xh);
    cudaGetSymbolAddress((void**)&xl, g_xl);
    cudaGetSymbolAddress((void**)&wh, g_wh);
    cudaGetSymbolAddress((void**)&wl, g_wl);
    cudaGetSymbolAddress((void**)&whhh, g_whhh);
    cudaGetSymbolAddress((void**)&whhl, g_whhl);
    cudaGetSymbolAddress(&barp, g_bar);

    const size_t nX  = (size_t)BB * SS * HH / 4;
    const size_t nW  = (size_t)GG * HH / 4;
    // Launch order arranged so k_gru_mma is launch index 5 (ncu -s 5 -c 1).
    k_split<<<(unsigned)((nX + 255) / 256), 256>>>(reps, xh, xl, nX);
    k_split<<<(unsigned)((nW + 255) / 256), 256>>>(W_ih, wh, wl, nW);
    k_split<<<(unsigned)((nW + 255) / 256), 256>>>(W_hh, whhh, whhl, nW);

    dim3 g1(800, 12);
    k_xproj_mma<<<g1, 256, XP_SMEM>>>(b_ih);
    cudaMemsetAsync(barp, 0, 16 * sizeof(unsigned));
    k_gru_mma<<<dim3(16, 8), 512, GRU_SMEM>>>(hidden, b_hh);
    k_attn_mma<<<BB, 256, AT_SMEM>>>(reps, counts, users, Wa, ba, Ws, out);
}

// round 16
// speedup vs baseline: 1.0836x; 1.0139x over previous
#include <cuda_runtime.h>
#include <cuda_bf16.h>
#include <math.h>
#include <stdint.h>

#define BB 1024
#define SS 100
#define HH 512
#define GG 1536   // 3*H
#define NUSR 1000

// ---------------------------------------------------------------------------
// Scratch (device globals: allowed; no runtime allocation)
// ---------------------------------------------------------------------------
__device__ float g_xproj[(size_t)BB * SS * GG];            // [B,S,3H] fp32
__device__ __nv_bfloat16 g_xh[(size_t)BB * SS * HH];       // X hi
__device__ __nv_bfloat16 g_xl[(size_t)BB * SS * HH];       // X lo
__device__ __nv_bfloat16 g_wh[(size_t)GG * HH];            // W_ih hi
__device__ __nv_bfloat16 g_wl[(size_t)GG * HH];            // W_ih lo
__device__ __nv_bfloat16 g_whhh[(size_t)GG * HH];          // W_hh hi
__device__ __nv_bfloat16 g_whhl[(size_t)GG * HH];          // W_hh lo
__device__ __nv_bfloat16 g_hh[(size_t)BB * 128 * HH];      // h for attention, hi (rows 100..127 stay 0)
__device__ __nv_bfloat16 g_hl[(size_t)BB * 128 * HH];      // h for attention, lo
__device__ __nv_bfloat16 g_hbh[(size_t)2 * BB * HH];       // h double buffer, hi
__device__ __nv_bfloat16 g_hbl[(size_t)2 * BB * HH];       // h double buffer, lo
__device__ float g_hstate[(size_t)BB * HH];                // exact fp32 h
__device__ unsigned g_bar[16];                             // spin barriers (memset each launch)

// ---------------------------------------------------------------------------
// Portable tensor-core primitives (compile for compute_103, no 'a' features)
// ---------------------------------------------------------------------------
__device__ __forceinline__ uint32_t smem_u32(const void* p) {
    uint32_t a;
    asm("{ .reg .u64 t; cvta.to.shared.u64 t, %1; cvt.u32.u64 %0, t; }"
        : "=r"(a) : "l"(p));
    return a;
}

#define CP_ASYNC16(sa, ga) \
    asm volatile("cp.async.cg.shared.global [%0], [%1], 16;" :: "r"(sa), "l"(ga))
#define CP_COMMIT() asm volatile("cp.async.commit_group;")
#define CP_WAIT1() asm volatile("cp.async.wait_group 1;" ::: "memory")
#define CP_WAIT0() asm volatile("cp.async.wait_group 0;" ::: "memory")

#define LDMX4(r0, r1, r2, r3, a) \
    asm volatile("ldmatrix.sync.aligned.m8n8.x4.shared.b16 {%0,%1,%2,%3}, [%4];" \
                 : "=r"(r0), "=r"(r1), "=r"(r2), "=r"(r3) : "r"(a))

#define LDMX2(r0, r1, a) \
    asm volatile("ldmatrix.sync.aligned.m8n8.x2.shared.b16 {%0,%1}, [%2];" \
                 : "=r"(r0), "=r"(r1) : "r"(a))

#define MMA_BF16(d, a, b) \
    asm volatile( \
        "mma.sync.aligned.m16n8k16.row.col.f32.bf16.bf16.f32 " \
        "{%0,%1,%2,%3}, {%4,%5,%6,%7}, {%8,%9}, {%0,%1,%2,%3};" \
        : "+f"((d)[0]), "+f"((d)[1]), "+f"((d)[2]), "+f"((d)[3]) \
        : "r"((a)[0]), "r"((a)[1]), "r"((a)[2]), "r"((a)[3]), \
          "r"((b)[0]), "r"((b)[1]))

// fp32 -> bf16 hi/lo split of 8 values, packed as uint4 each
__device__ __forceinline__ void cvt8(const float* f, uint4& hv, uint4& lv) {
    union { __nv_bfloat16 h[8]; uint4 u; } H;
    union { __nv_bfloat16 h[8]; uint4 u; } L;
#pragma unroll
    for (int j = 0; j < 8; j++) {
        __nv_bfloat16 hh = __float2bfloat16(f[j]);
        H.h[j] = hh;
        L.h[j] = __float2bfloat16(f[j] - __bfloat162float(hh));
    }
    hv = H.u; lv = L.u;
}

// ---------------------------------------------------------------------------
// Kernel A: fp32 -> bf16 hi/lo split (generic, float4-granular)
// ---------------------------------------------------------------------------
__global__ void k_split(const float* __restrict__ src, __nv_bfloat16* __restrict__ hi,
                        __nv_bfloat16* __restrict__ lo, size_t n4) {
    size_t i = (size_t)blockIdx.x * 256 + threadIdx.x;
    if (i >= n4) return;
    float4 v = ((const float4*)src)[i];
    float f[4] = {v.x, v.y, v.z, v.w};
    union { __nv_bfloat16 h[4]; uint2 u; } H;
    union { __nv_bfloat16 h[4]; uint2 u; } L;
#pragma unroll
    for (int j = 0; j < 4; j++) {
        __nv_bfloat16 hh = __float2bfloat16(f[j]);
        H.h[j] = hh;
        L.h[j] = __float2bfloat16(f[j] - __bfloat162float(hh));
    }
    *(uint2*)(hi + i * 4) = H.u;
    *(uint2*)(lo + i * 4) = L.u;
}

// ---------------------------------------------------------------------------
// Kernel 1: x_proj = X @ W_ih^T + b_ih  via mma.sync bf16 split-3.
// R16: grid axes swapped -> bn = blockIdx.x (fastest), bm = blockIdx.y.
// Co-resident CTAs now share each bm's X tile in L2: X is DRAM-read ONCE
// (420 MB) instead of 12x (2.5 GB).  Otherwise identical to R15 (256 thr,
// 128x128 tile, 3-stage cp.async ring, 2 CTAs/SM).
// ---------------------------------------------------------------------------
#define XP_AH 0
#define XP_AL 6144
#define XP_BH 12288
#define XP_BL 18432
#define XP_STG 24576
#define XP_SMEM (3 * XP_STG)

__global__ void __launch_bounds__(256, 2)
k_xproj_mma(const float* __restrict__ bias) {
    extern __shared__ char smx[];
    const uint32_t sb = smem_u32(smx);
    const int tid = threadIdx.x;
    const int wid = tid >> 5, lane = tid & 31;
    const int wm = wid >> 2, wn = wid & 3;      // 2m x 4n warps, warp tile 64x32
    const int bn = blockIdx.x;                  // 0..11  (fastest -> L2 reuse of X)
    const int bm = blockIdx.y;                  // 0..799
    const size_t m0 = (size_t)bm * 128;
    const size_t n0 = (size_t)bn * 128;

    const int tr = tid >> 1, tc = tid & 1;      // cp.async: 128 rows x 2 halves

    float acc[4][4][4];
#pragma unroll
    for (int i = 0; i < 4; i++)
#pragma unroll
        for (int j = 0; j < 4; j++)
#pragma unroll
            for (int q = 0; q < 4; q++) acc[i][j][q] = 0.f;

    const uint32_t a_lane_off =
        (uint32_t)((wm * 64 + (lane & 15)) * 48 + (lane >> 4) * 16);
    const uint32_t b_lane_off =
        (uint32_t)((wn * 32 + (lane & 7) + (lane >> 4) * 8) * 48 +
                   ((lane >> 3) & 1) * 16);

    // prologue: issue stages 0 and 1 (two groups in flight)
#pragma unroll
    for (int s = 0; s < 2; s++) {
        uint32_t st = sb + (uint32_t)s * XP_STG;
        const int k0 = s * 16;
        CP_ASYNC16(st + XP_AH + tr * 48 + tc * 16,
                   g_xh + (m0 + tr) * 512 + k0 + tc * 8);
        CP_ASYNC16(st + XP_AL + tr * 48 + tc * 16,
                   g_xl + (m0 + tr) * 512 + k0 + tc * 8);
        CP_ASYNC16(st + XP_BH + tr * 48 + tc * 16,
                   g_wh + (n0 + tr) * 512 + k0 + tc * 8);
        CP_ASYNC16(st + XP_BL + tr * 48 + tc * 16,
                   g_wl + (n0 + tr) * 512 + k0 + tc * 8);
        CP_COMMIT();
    }

    int slot = 0, slot2 = 2;                    // slot = c%3, slot2 = (c+2)%3
    for (int c = 0; c < 32; c++) {
        if (c < 31) CP_WAIT1(); else CP_WAIT0();
        __syncthreads();
        if (c + 2 < 32) {
            const int k0 = (c + 2) * 16;
            uint32_t st = sb + (uint32_t)slot2 * XP_STG;
            CP_ASYNC16(st + XP_AH + tr * 48 + tc * 16,
                       g_xh + (m0 + tr) * 512 + k0 + tc * 8);
            CP_ASYNC16(st + XP_AL + tr * 48 + tc * 16,
                       g_xl + (m0 + tr) * 512 + k0 + tc * 8);
            CP_ASYNC16(st + XP_BH + tr * 48 + tc * 16,
                       g_wh + (n0 + tr) * 512 + k0 + tc * 8);
            CP_ASYNC16(st + XP_BL + tr * 48 + tc * 16,
                       g_wl + (n0 + tr) * 512 + k0 + tc * 8);
            CP_COMMIT();
        }
        const uint32_t cur = sb + (uint32_t)slot * XP_STG;

        uint32_t bh[4][2], bl[4][2];
        {
            uint32_t r0, r1, r2, r3;
            LDMX4(r0, r1, r2, r3, cur + XP_BH + b_lane_off);
            bh[0][0] = r0; bh[0][1] = r1; bh[1][0] = r2; bh[1][1] = r3;
            LDMX4(r0, r1, r2, r3, cur + XP_BH + b_lane_off + 16 * 48);
            bh[2][0] = r0; bh[2][1] = r1; bh[3][0] = r2; bh[3][1] = r3;
            LDMX4(r0, r1, r2, r3, cur + XP_BL + b_lane_off);
            bl[0][0] = r0; bl[0][1] = r1; bl[1][0] = r2; bl[1][1] = r3;
            LDMX4(r0, r1, r2, r3, cur + XP_BL + b_lane_off + 16 * 48);
            bl[2][0] = r0; bl[2][1] = r1; bl[3][0] = r2; bl[3][1] = r3;
        }
#pragma unroll
        for (int mi = 0; mi < 4; mi++) {
            uint32_t ah[4], al[4];
            LDMX4(ah[0], ah[1], ah[2], ah[3], cur + XP_AH + a_lane_off + mi * 16 * 48);
            LDMX4(al[0], al[1], al[2], al[3], cur + XP_AL + a_lane_off + mi * 16 * 48);
#pragma unroll
            for (int nj = 0; nj < 4; nj++) {
                MMA_BF16(acc[mi][nj], ah, bh[nj]);
                MMA_BF16(acc[mi][nj], ah, bl[nj]);
                MMA_BF16(acc[mi][nj], al, bh[nj]);
            }
        }
        slot = (slot == 2) ? 0 : slot + 1;
        slot2 = (slot2 == 2) ? 0 : slot2 + 1;
    }

    const int q = lane >> 2, cc = (lane & 3) * 2;
#pragma unroll
    for (int mi = 0; mi < 4; mi++) {
        const size_t r0 = m0 + wm * 64 + mi * 16 + q;
#pragma unroll
        for (int nj = 0; nj < 4; nj++) {
            const size_t nn = n0 + wn * 32 + nj * 8 + cc;
            float b0 = __ldg(bias + nn), b1 = __ldg(bias + nn + 1);
            float2 v0 = {acc[mi][nj][0] + b0, acc[mi][nj][1] + b1};
            float2 v1 = {acc[mi][nj][2] + b0, acc[mi][nj][3] + b1};
            *(float2*)(g_xproj + r0 * GG + nn) = v0;
            *(float2*)(g_xproj + (r0 + 8) * GG + nn) = v1;
        }
    }
}

// ---------------------------------------------------------------------------
// Kernel 2: persistent mma GRU (byte-identical to the 4,750us passing R15).
// ---------------------------------------------------------------------------
#define GRU_WH 0
#define GRU_WL 98304
#define GRU_AST 196608
#define GRU_SMEM (196608 + 24576)

__global__ void __launch_bounds__(512, 1)
k_gru_mma(const float* __restrict__ h0, const float* __restrict__ bhh) {
    extern __shared__ char smx[];
    const uint32_t sb = smem_u32(smx);
    const int tid = threadIdx.x;
    const int wid = tid >> 5, lane = tid & 31;
    const int wm = wid >> 2, wn = wid & 3;     // 4 x 4 warps
    const int ns = blockIdx.x;
    const int mt = blockIdx.y;
    const int cid = mt * 16 + ns;
    const int mrow0 = mt * 128;

#pragma unroll
    for (int qq = 0; qq < 12; qq++) {
        int gi = tid + 512 * qq;
        int lr = gi >> 6, g16 = gi & 63;
        int grow = (lr >> 5) * 512 + ns * 32 + (lr & 31);
        uint32_t phys = (uint32_t)lr * 1024 + (uint32_t)((g16 ^ (lr & 7)) << 4);
        CP_ASYNC16(sb + GRU_WH + phys, g_whhh + (size_t)grow * 512 + g16 * 8);
        CP_ASYNC16(sb + GRU_WL + phys, g_whhl + (size_t)grow * 512 + g16 * 8);
    }
    CP_COMMIT();

#pragma unroll
    for (int qq = 0; qq < 2; qq++) {
        int idx = tid + 512 * qq;
        int r = idx >> 7, cp4 = (idx & 127) * 4;
        size_t o = (size_t)(cid * 8 + r) * 512 + cp4;
        float4 v = *(const float4*)(h0 + o);
        *(float4*)(g_hstate + o) = v;
        float f[4] = {v.x, v.y, v.z, v.w};
        union { __nv_bfloat16 h[4]; uint2 u; } H;
        union { __nv_bfloat16 h[4]; uint2 u; } L;
#pragma unroll
        for (int j = 0; j < 4; j++) {
            __nv_bfloat16 hh = __float2bfloat16(f[j]);
            H.h[j] = hh;
            L.h[j] = __float2bfloat16(f[j] - __bfloat162float(hh));
        }
        *(uint2*)(g_hbh + o) = H.u;
        *(uint2*)(g_hbl + o) = L.u;
    }
    __threadfence();
    __syncthreads();
    if (tid == 0) {
        atomicAdd(&g_bar[8], 1u);
        volatile unsigned* p = &g_bar[8];
        while (*p < 128u) {}
    }
    __syncthreads();
    __threadfence();
    CP_WAIT0();
    __syncthreads();

    const int ar = tid & 255, ahf = (ar & 1);
    const int arow = ar >> 1;
    const bool isAlo = (tid >= 256);
    const uint32_t a_cp_dst = (isAlo ? 6144u : 0u) + arow * 48 + ahf * 16;
    const __nv_bfloat16* g_hb_sel[2] = {g_hbh, g_hbl};

    const uint32_t a_base =
        (uint32_t)((wm * 32 + (lane & 15)) * 48 + (lane >> 4) * 16);
    int lrB[3];
#pragma unroll
    for (int g = 0; g < 3; g++) lrB[g] = g * 32 + wn * 8 + (lane & 7);
    const int kbit = (lane >> 3) & 1;
    const int qrow = lane >> 2, cc = (lane & 3) * 2;
    const int c0 = ns * 32 + wn * 8 + cc;
    float bhg[3][2];
#pragma unroll
    for (int g = 0; g < 3; g++) {
        bhg[g][0] = __ldg(bhh + g * 512 + c0);
        bhg[g][1] = __ldg(bhh + g * 512 + c0 + 1);
    }

    unsigned bar_target = 16;
    for (int t = 0; t < SS; t++) {
        const int cur = t & 1, nxt = cur ^ 1;
        const __nv_bfloat16* hsrc =
            g_hb_sel[isAlo ? 1 : 0] + (size_t)cur * (BB * HH);

        {
            uint32_t st = sb + GRU_AST;
            CP_ASYNC16(st + a_cp_dst,
                       hsrc + (size_t)(mrow0 + arow) * 512 + ahf * 8);
            CP_COMMIT();
        }

        float acc[2][3][4];
#pragma unroll
        for (int i = 0; i < 2; i++)
#pragma unroll
            for (int g = 0; g < 3; g++)
#pragma unroll
                for (int z = 0; z < 4; z++) acc[i][g][z] = 0.f;

        for (int c = 0; c < 32; c++) {
            CP_WAIT0();
            __syncthreads();
            if (c < 31) {
                uint32_t st = sb + GRU_AST + (uint32_t)((c + 1) & 1) * 12288;
                const int kb = (c + 1) * 16 + ahf * 8;
                CP_ASYNC16(st + a_cp_dst,
                           hsrc + (size_t)(mrow0 + arow) * 512 + kb);
                CP_COMMIT();
            }
            const uint32_t cs = sb + GRU_AST + (uint32_t)(c & 1) * 12288;

            uint32_t bhf[3][2], blf[3][2];
#pragma unroll
            for (int g = 0; g < 3; g++) {
                int g16 = 2 * c + kbit;
                uint32_t phys = (uint32_t)lrB[g] * 1024 +
                                (uint32_t)((g16 ^ (lrB[g] & 7)) << 4);
                LDMX2(bhf[g][0], bhf[g][1], sb + GRU_WH + phys);
                LDMX2(blf[g][0], blf[g][1], sb + GRU_WL + phys);
            }
#pragma unroll
            for (int mi = 0; mi < 2; mi++) {
                uint32_t ah[4], al[4];
                LDMX4(ah[0], ah[1], ah[2], ah[3], cs + a_base + mi * 768);
                LDMX4(al[0], al[1], al[2], al[3], cs + 6144 + a_base + mi * 768);
#pragma unroll
                for (int g = 0; g < 3; g++) {
                    MMA_BF16(acc[mi][g], ah, bhf[g]);
                    MMA_BF16(acc[mi][g], ah, blf[g]);
                    MMA_BF16(acc[mi][g], al, bhf[g]);
                }
            }
        }
        __syncthreads();

#pragma unroll
        for (int mi = 0; mi < 2; mi++) {
#pragma unroll
            for (int hp = 0; hp < 2; hp++) {
                const int b = mrow0 + wm * 32 + mi * 16 + qrow + hp * 8;
                const size_t xb = ((size_t)b * SS + t) * GG + c0;
                float xr0 = g_xproj[xb],        xr1 = g_xproj[xb + 1];
                float xz0 = g_xproj[xb + 512],  xz1 = g_xproj[xb + 513];
                float xn0 = g_xproj[xb + 1024], xn1 = g_xproj[xb + 1025];
                float2 hold = *(const float2*)(g_hstate + (size_t)b * 512 + c0);
                float hr0 = acc[mi][0][hp * 2 + 0] + bhg[0][0];
                float hr1 = acc[mi][0][hp * 2 + 1] + bhg[0][1];
                float hz0 = acc[mi][1][hp * 2 + 0] + bhg[1][0];
                float hz1 = acc[mi][1][hp * 2 + 1] + bhg[1][1];
                float hn0 = acc[mi][2][hp * 2 + 0] + bhg[2][0];
                float hn1 = acc[mi][2][hp * 2 + 1] + bhg[2][1];
                float rg0 = 1.f / (1.f + expf(-(xr0 + hr0)));
                float rg1 = 1.f / (1.f + expf(-(xr1 + hr1)));
                float zg0 = 1.f / (1.f + expf(-(xz0 + hz0)));
                float zg1 = 1.f / (1.f + expf(-(xz1 + hz1)));
                float ng0 = tanhf(xn0 + rg0 * hn0);
                float ng1 = tanhf(xn1 + rg1 * hn1);
                float h0n = (1.f - zg0) * ng0 + zg0 * hold.x;
                float h1n = (1.f - zg1) * ng1 + zg1 * hold.y;
                float2 hsv = {h0n, h1n};
                *(float2*)(g_hstate + (size_t)b * 512 + c0) = hsv;
                __nv_bfloat16 p0 = __float2bfloat16(h0n);
                __nv_bfloat16 p1 = __float2bfloat16(h1n);
                __nv_bfloat16 q0 = __float2bfloat16(h0n - __bfloat162float(p0));
                __nv_bfloat16 q1 = __float2bfloat16(h1n - __bfloat162float(p1));
                __nv_bfloat162 ph = __halves2bfloat162(p0, p1);
                __nv_bfloat162 pl = __halves2bfloat162(q0, q1);
                size_t ob = (size_t)nxt * (BB * HH) + (size_t)b * 512 + c0;
                *(__nv_bfloat162*)(g_hbh + ob) = ph;
                *(__nv_bfloat162*)(g_hbl + ob) = pl;
                size_t oa = ((size_t)b * 128 + t) * 512 + c0;
                *(__nv_bfloat162*)(g_hh + oa) = ph;
                *(__nv_bfloat162*)(g_hl + oa) = pl;
            }
        }
        __threadfence();
        __syncthreads();
        if (tid == 0) {
            atomicAdd(&g_bar[mt], 1u);
            volatile unsigned* p = &g_bar[mt];
            while (*p < bar_target) {}
        }
        __syncthreads();
        __threadfence();
        bar_target += 16;
    }
}

// ---------------------------------------------------------------------------
// Kernel 3: attention via mma.sync (byte-identical to the 4,750us passing R15).
// ---------------------------------------------------------------------------
#define AT_BA 0
#define AT_WS 2048
#define AT_CS 4096
#define AT_SC 4608
#define AT_BASE 5120
#define AT_AH 0
#define AT_AL 6144
#define AT_BF 12288
#define AT_BH 22528
#define AT_BL 28672
#define AT_STG 34816
#define AT_SMEM (AT_BASE + 2 * AT_STG)

__global__ void __launch_bounds__(256, 1)
k_attn_mma(const float* __restrict__ reps, const int* __restrict__ counts,
           const int* __restrict__ users, const float* __restrict__ Wa,
           const float* __restrict__ ba, const float* __restrict__ Wsv,
           float* __restrict__ outp) {
    extern __shared__ char smx[];
    const uint32_t sb = smem_u32(smx);
    float* ba_s  = (float*)(smx + AT_BA);
    float* ws_s  = (float*)(smx + AT_WS);
    float* C_s   = (float*)(smx + AT_CS);
    float* score = (float*)(smx + AT_SC);
    const int tid = threadIdx.x;
    const int wid = tid >> 5, lane = tid & 31;
    const int wm = wid >> 2, wn = wid & 3;
    const int b = blockIdx.x;
    const int cnt = counts[b];
    const int u = users[b];

    ba_s[tid]       = ba[(size_t)u * 512 + tid];
    ba_s[tid + 256] = ba[(size_t)u * 512 + 256 + tid];
    ws_s[tid]       = Wsv[(size_t)u * 512 + tid];
    ws_s[tid + 256] = Wsv[(size_t)u * 512 + 256 + tid];
    if (tid < 128) score[tid] = 0.f;
    __syncthreads();

    const __nv_bfloat16* Ahg = g_hh + (size_t)b * 128 * 512;
    const __nv_bfloat16* Alg = g_hl + (size_t)b * 128 * 512;
    const float* Bg = Wa + (size_t)u * 512 * 512;

    const int tr = tid >> 1, tc = tid & 1;
    const uint32_t a_lane_off =
        (uint32_t)((wm * 64 + (lane & 15)) * 48 + (lane >> 4) * 16);
    const uint32_t b_lane_off =
        (uint32_t)((wn * 32 + (lane & 7) + (lane >> 4) * 8) * 48 +
                   ((lane >> 3) & 1) * 16);
    const int q = lane >> 2, cc = (lane & 3) * 2;
    const int mimax = (wm == 0) ? 4 : 3;

    {
        uint32_t st = sb + AT_BASE;
        CP_ASYNC16(st + AT_AH + tr * 48 + tc * 16, Ahg + tr * 512 + tc * 8);
        CP_ASYNC16(st + AT_AL + tr * 48 + tc * 16, Alg + tr * 512 + tc * 8);
        CP_ASYNC16(st + AT_BF + tr * 80 + tc * 32,      Bg + (size_t)tr * 512 + tc * 8);
        CP_ASYNC16(st + AT_BF + tr * 80 + tc * 32 + 16, Bg + (size_t)tr * 512 + tc * 8 + 4);
        CP_COMMIT();
    }

    float acc[4][4][4];
    float cacc = 0.f;
    for (int it = 0; it < 128; it++) {
        const int np = it >> 5, c = it & 31;
        if (c == 0) {
#pragma unroll
            for (int i = 0; i < 4; i++)
#pragma unroll
                for (int j = 0; j < 4; j++)
#pragma unroll
                    for (int z = 0; z < 4; z++) acc[i][j][z] = 0.f;
            cacc = 0.f;
        }
        char* stc = smx + AT_BASE + (size_t)(it & 1) * AT_STG;
        const uint32_t cur = sb + AT_BASE + (uint32_t)(it & 1) * AT_STG;
        if (it < 127) {
            const int np2 = (it + 1) >> 5, c2 = (it + 1) & 31;
            const int k0 = c2 * 16;
            uint32_t st = sb + AT_BASE + (uint32_t)((it + 1) & 1) * AT_STG;
            const float* brow = Bg + (size_t)(np2 * 128 + tr) * 512 + k0 + tc * 8;
            CP_ASYNC16(st + AT_AH + tr * 48 + tc * 16,
                       Ahg + tr * 512 + k0 + tc * 8);
            CP_ASYNC16(st + AT_AL + tr * 48 + tc * 16,
                       Alg + tr * 512 + k0 + tc * 8);
            CP_ASYNC16(st + AT_BF + tr * 80 + tc * 32, brow);
            CP_ASYNC16(st + AT_BF + tr * 80 + tc * 32 + 16, brow + 4);
            CP_COMMIT();
            CP_WAIT1();
        } else {
            CP_WAIT0();
        }
        __syncthreads();

        {
            float4 v0 = *(const float4*)(stc + AT_BF + tr * 80 + tc * 32);
            float4 v1 = *(const float4*)(stc + AT_BF + tr * 80 + tc * 32 + 16);
            float f[8] = {v0.x, v0.y, v0.z, v0.w, v1.x, v1.y, v1.z, v1.w};
            cacc += f[0] + f[1] + f[2] + f[3] + f[4] + f[5] + f[6] + f[7];
            uint4 hv, lv;
            cvt8(f, hv, lv);
            *(uint4*)(stc + AT_BH + tr * 48 + tc * 16) = hv;
            *(uint4*)(stc + AT_BL + tr * 48 + tc * 16) = lv;
        }
        if (c == 31) {
            float tot = cacc + __shfl_xor_sync(0xffffffffu, cacc, 1);
            if (tc == 0) C_s[tr] = tot;
        }
        __syncthreads();

        uint32_t bh[4][2], bl[4][2];
        {
            uint32_t r0, r1, r2, r3;
            LDMX4(r0, r1, r2, r3, cur + AT_BH + b_lane_off);
            bh[0][0] = r0; bh[0][1] = r1; bh[1][0] = r2; bh[1][1] = r3;
            LDMX4(r0, r1, r2, r3, cur + AT_BH + b_lane_off + 16 * 48);
            bh[2][0] = r0; bh[2][1] = r1; bh[3][0] = r2; bh[3][1] = r3;
            LDMX4(r0, r1, r2, r3, cur + AT_BL + b_lane_off);
            bl[0][0] = r0; bl[0][1] = r1; bl[1][0] = r2; bl[1][1] = r3;
            LDMX4(r0, r1, r2, r3, cur + AT_BL + b_lane_off + 16 * 48);
            bl[2][0] = r0; bl[2][1] = r1; bl[3][0] = r2; bl[3][1] = r3;
        }
#pragma unroll
        for (int mi = 0; mi < 4; mi++) {
            if (mi >= mimax) break;
            uint32_t ah[4], al[4];
            LDMX4(ah[0], ah[1], ah[2], ah[3], cur + AT_AH + a_lane_off + mi * 16 * 48);
            LDMX4(al[0], al[1], al[2], al[3], cur + AT_AL + a_lane_off + mi * 16 * 48);
#pragma unroll
            for (int nj = 0; nj < 4; nj++) {
                MMA_BF16(acc[mi][nj], ah, bh[nj]);
                MMA_BF16(acc[mi][nj], ah, bl[nj]);
                MMA_BF16(acc[mi][nj], al, bh[nj]);
            }
        }

        if (c == 31) {
#pragma unroll
            for (int mi = 0; mi < 4; mi++) {
                if (mi >= mimax) break;
                const int s0 = wm * 64 + mi * 16 + q;
#pragma unroll
                for (int half = 0; half < 2; half++) {
                    const int s = s0 + half * 8;
                    const bool valid = (s < 100);
                    const float msk = (valid && s >= cnt) ? 1000000.0f : 0.0f;
                    float psum = 0.f;
#pragma unroll
                    for (int nj = 0; nj < 4; nj++) {
                        const int ol = wn * 32 + nj * 8 + cc;
                        const int o0 = np * 128 + ol;
                        float a0 = acc[mi][nj][half * 2 + 0] + ba_s[o0] - msk * C_s[ol];
                        float a1 = acc[mi][nj][half * 2 + 1] + ba_s[o0 + 1] - msk * C_s[ol + 1];
                        psum += ws_s[o0] * tanhf(a0) + ws_s[o0 + 1] * tanhf(a1);
                    }
                    psum += __shfl_xor_sync(0xffffffffu, psum, 1);
                    psum += __shfl_xor_sync(0xffffffffu, psum, 2);
                    if ((lane & 3) == 0 && valid) atomicAdd(&score[s], psum);
                }
            }
        }
    }
    __syncthreads();

    if (tid < 32) {
        float mx = -1e30f;
        for (int s = tid; s < 100; s += 32) mx = fmaxf(mx, score[s]);
#pragma unroll
        for (int o = 16; o > 0; o >>= 1) mx = fmaxf(mx, __shfl_xor_sync(0xffffffffu, mx, o));
        float ssum = 0.f;
        for (int s = tid; s < 100; s += 32) {
            float e = expf(score[s] - mx);
            score[s] = e;
            ssum += e;
        }
#pragma unroll
        for (int o = 16; o > 0; o >>= 1) ssum += __shfl_xor_sync(0xffffffffu, ssum, o);
        float inv = 1.f / ssum;
        for (int s = tid; s < 100; s += 32) score[s] *= inv;
    }
    __syncthreads();

    const float* rb = reps + (size_t)b * (SS * HH);
    for (int h = tid; h < 512; h += 256) {
        float a0 = 0.f;
        for (int s = 0; s < 100; s++) a0 += score[s] * rb[s * 512 + h];
        outp[(size_t)b * 512 + h] = a0;
    }
}

// ---------------------------------------------------------------------------
extern "C" void kernel_launch(void* const* d_in, const int* in_sizes, int n_in,
                              void* d_out, int out_size) {
    const float* reps   = (const float*)d_in[0];
    const float* hidden = (const float*)d_in[1];
    const int*   counts = (const int*)d_in[2];
    const int*   users  = (const int*)d_in[3];
    const float* W_ih   = (const float*)d_in[4];
    const float* W_hh   = (const float*)d_in[5];
    const float* b_ih   = (const float*)d_in[6];
    const float* b_hh   = (const float*)d_in[7];
    const float* Wa     = (const float*)d_in[8];
    const float* ba     = (const float*)d_in[9];
    const float* Ws     = (const float*)d_in[10];
    // d_in[11] = bs: additive per-row constant on scores -> softmax-invariant.
    float* out = (float*)d_out;

    cudaFuncSetAttribute(k_xproj_mma, cudaFuncAttributeMaxDynamicSharedMemorySize,
                         XP_SMEM);
    cudaFuncSetAttribute(k_gru_mma, cudaFuncAttributeMaxDynamicSharedMemorySize,
                         GRU_SMEM);
    cudaFuncSetAttribute(k_attn_mma, cudaFuncAttributeMaxDynamicSharedMemorySize,
                         AT_SMEM);

    __nv_bfloat16 *xh, *xl, *wh, *wl, *whhh, *whhl;
    void* barp;
    cudaGetSymbolAddress((void**)&xh, g_xh);
    cudaGetSymbolAddress((void**)&xl, g_xl);
    cudaGetSymbolAddress((void**)&wh, g_wh);
    cudaGetSymbolAddress((void**)&wl, g_wl);
    cudaGetSymbolAddress((void**)&whhh, g_whhh);
    cudaGetSymbolAddress((void**)&whhl, g_whhl);
    cudaGetSymbolAddress(&barp, g_bar);

    const size_t nX  = (size_t)BB * SS * HH / 4;
    const size_t nW  = (size_t)GG * HH / 4;
    // Launch order arranged so k_gru_mma is launch index 5 (ncu -s 5 -c 1).
    k_split<<<(unsigned)((nX + 255) / 256), 256>>>(reps, xh, xl, nX);
    k_split<<<(unsigned)((nW + 255) / 256), 256>>>(W_ih, wh, wl, nW);
    k_split<<<(unsigned)((nW + 255) / 256), 256>>>(W_hh, whhh, whhl, nW);

    dim3 g1(12, 800);   // bn fastest -> X tiles shared in L2 across co-resident CTAs
    k_xproj_mma<<<g1, 256, XP_SMEM>>>(b_ih);
    cudaMemsetAsync(barp, 0, 16 * sizeof(unsigned));
    k_gru_mma<<<dim3(16, 8), 512, GRU_SMEM>>>(hidden, b_hh);
    k_attn_mma<<<BB, 256, AT_SMEM>>>(reps, counts, users, Wa, ba, Ws, out);
}